// round 4
// baseline (speedup 1.0000x reference)
#include <cuda_runtime.h>
#include <cuda_bf16.h>
#include <cstdint>

// Problem constants (fixed shapes)
constexpr int B_  = 2;
constexpr int S_  = 2048;
constexpr int D_  = 1024;
constexpr int H_  = 16;
constexpr int M_  = B_ * S_;            // 4096
constexpr size_t SS_ = (size_t)S_ * S_; // 4M

// ---------------------------------------------------------------------------
// Device-global scratch
// ---------------------------------------------------------------------------
__device__ float g_v[(size_t)M_ * D_];
__device__ float g_att[(size_t)B_ * H_ * SS_];            // 512 MB fp32 scores

__device__ __nv_bfloat16 g_qi_hi[(size_t)M_ * D_], g_qi_lo[(size_t)M_ * D_];
__device__ __nv_bfloat16 g_ki_hi[(size_t)M_ * D_], g_ki_lo[(size_t)M_ * D_];
__device__ __nv_bfloat16 g_vi_hi[(size_t)M_ * D_], g_vi_lo[(size_t)M_ * D_];
__device__ __nv_bfloat16 g_q_hi [(size_t)M_ * D_], g_q_lo [(size_t)M_ * D_];
__device__ __nv_bfloat16 g_k_hi [(size_t)M_ * D_], g_k_lo [(size_t)M_ * D_];
__device__ __nv_bfloat16 g_x_hi [(size_t)M_ * D_], g_x_lo [(size_t)M_ * D_];
__device__ __nv_bfloat16 g_vt_hi[(size_t)B_ * H_ * 64 * S_];  // [bh][64][2048]
__device__ __nv_bfloat16 g_vt_lo[(size_t)B_ * H_ * 64 * S_];
__device__ __nv_bfloat16 g_wq_hi[(size_t)D_ * D_], g_wq_lo[(size_t)D_ * D_];
__device__ __nv_bfloat16 g_wk_hi[(size_t)D_ * D_], g_wk_lo[(size_t)D_ * D_];
__device__ __nv_bfloat16 g_wv_hi[(size_t)D_ * D_], g_wv_lo[(size_t)D_ * D_];
__device__ __nv_bfloat16 g_wo_hi[(size_t)D_ * D_], g_wo_lo[(size_t)D_ * D_];

// ---------------------------------------------------------------------------
// PTX helpers (compute_103-baseline safe: mma.sync / ldmatrix / cp.async)
// ---------------------------------------------------------------------------
__device__ __forceinline__ uint32_t smem_u32(const void* p) {
    uint32_t a;
    asm("{ .reg .u64 t; cvta.to.shared.u64 t, %1; cvt.u32.u64 %0, t; }"
        : "=r"(a) : "l"(p));
    return a;
}
__device__ __forceinline__ void cp16(uint32_t dst, const void* src) {
    asm volatile("cp.async.cg.shared.global [%0], [%1], 16;"
                 :: "r"(dst), "l"(src));
}
#define CP_COMMIT() asm volatile("cp.async.commit_group;" ::: "memory")
#define CP_WAIT(n)  asm volatile("cp.async.wait_group %0;" :: "n"(n) : "memory")

#define LDSM_X4(r, addr)                                                       \
    asm volatile("ldmatrix.sync.aligned.m8n8.x4.shared.b16 {%0,%1,%2,%3},[%4];"\
                 : "=r"((r)[0]), "=r"((r)[1]), "=r"((r)[2]), "=r"((r)[3])      \
                 : "r"(addr))
#define LDSM_X2(r, addr)                                                       \
    asm volatile("ldmatrix.sync.aligned.m8n8.x2.shared.b16 {%0,%1},[%2];"      \
                 : "=r"((r)[0]), "=r"((r)[1]) : "r"(addr))
#define MMA16816(c, a, b)                                                      \
    asm volatile("mma.sync.aligned.m16n8k16.row.col.f32.bf16.bf16.f32 "        \
                 "{%0,%1,%2,%3},{%4,%5,%6,%7},{%8,%9},{%0,%1,%2,%3};"          \
                 : "+f"((c)[0]), "+f"((c)[1]), "+f"((c)[2]), "+f"((c)[3])      \
                 : "r"((a)[0]), "r"((a)[1]), "r"((a)[2]), "r"((a)[3]),         \
                   "r"((b)[0]), "r"((b)[1]))

__device__ __forceinline__ __nv_bfloat162 split_pair(float a, float b,
                                                     __nv_bfloat162& lo) {
    __nv_bfloat16 ha = __float2bfloat16(a);
    __nv_bfloat16 hb = __float2bfloat16(b);
    lo = __nv_bfloat162(__float2bfloat16(a - __bfloat162float(ha)),
                        __float2bfloat16(b - __bfloat162float(hb)));
    return __nv_bfloat162(ha, hb);
}

// ---------------------------------------------------------------------------
// fp32 -> (bf16 hi, bf16 lo) split, vectorized
// ---------------------------------------------------------------------------
__global__ __launch_bounds__(256) void split_bf16_kernel(
    const float4* __restrict__ x, __nv_bfloat162* __restrict__ hi,
    __nv_bfloat162* __restrict__ lo, int n4)
{
    int i = blockIdx.x * 256 + threadIdx.x;
    if (i >= n4) return;
    float4 v = x[i];
    __nv_bfloat162 l0, l1;
    __nv_bfloat162 h0 = split_pair(v.x, v.y, l0);
    __nv_bfloat162 h1 = split_pair(v.z, v.w, l1);
    hi[2 * i] = h0; hi[2 * i + 1] = h1;
    lo[2 * i] = l0; lo[2 * i + 1] = l1;
}

// ---------------------------------------------------------------------------
// V [b, k(2048), d(1024)] fp32  ->  Vt hi/lo [bh, d(64), k(2048)] bf16
// ---------------------------------------------------------------------------
__global__ __launch_bounds__(256) void transpose_split_v(
    const float* __restrict__ V, __nv_bfloat16* __restrict__ hi,
    __nv_bfloat16* __restrict__ lo)
{
    __shared__ float t[32][33];
    const int b  = blockIdx.z;
    const int k0 = blockIdx.y * 32;
    const int d0 = blockIdx.x * 32;
    const int tx = threadIdx.x & 31, ty = threadIdx.x >> 5;  // 32 x 8
#pragma unroll
    for (int i = 0; i < 4; i++) {
        int k = k0 + ty + i * 8;
        t[ty + i * 8][tx] = V[((size_t)b * S_ + k) * D_ + d0 + tx];
    }
    __syncthreads();
#pragma unroll
    for (int i = 0; i < 4; i++) {
        int d = d0 + ty + i * 8;
        int h = d >> 6, dh = d & 63;
        float val = t[tx][ty + i * 8];
        size_t o = ((size_t)(b * H_ + h) * 64 + dh) * S_ + k0 + tx;
        __nv_bfloat16 hv = __float2bfloat16(val);
        hi[o] = hv;
        lo[o] = __float2bfloat16(val - __bfloat162float(hv));
    }
}

// ---------------------------------------------------------------------------
// Generic NT bf16x3 GEMM: C[M,N](+scale) = (Ahi+Alo)[M,K] @ (Bhi+Blo)[N,K]^T
// OUT16=0: fp32 C.  OUT16=1: bf16 hi/lo (Chi, Clo).
// ---------------------------------------------------------------------------
template<int BN, int WGM, int WGN, int OUT16>
__global__ __launch_bounds__(256, 1) void gemm_bf16x3_mma(
    const __nv_bfloat16* __restrict__ Ahi, const __nv_bfloat16* __restrict__ Alo,
    const __nv_bfloat16* __restrict__ Bhi, const __nv_bfloat16* __restrict__ Blo,
    float* __restrict__ C, __nv_bfloat16* __restrict__ Chi,
    __nv_bfloat16* __restrict__ Clo, int K, int lda, int ldb, int ldc,
    size_t zsA1, size_t zsA2, size_t zsB1, size_t zsB2,
    size_t zsC1, size_t zsC2, float scale)
{
    constexpr int BM  = 128, BK = 32;
    constexpr int WTM = BM / WGM;
    constexpr int WTN = BN / WGN;
    constexpr int MT  = WTM / 16;
    constexpr int NT  = WTN / 8;
    constexpr int LDSR = BK + 8;
    constexpr int A_BYTES = BM * LDSR * 2;
    constexpr int B_BYTES = BN * LDSR * 2;
    constexpr int STAGE   = 2 * A_BYTES + 2 * B_BYTES;
    constexpr int CHUNKS  = (2 * BM + 2 * BN) * 4;

    extern __shared__ char smem_raw[];
    const uint32_t sbase = smem_u32(smem_raw);

    const int tid  = threadIdx.x;
    const int wid  = tid >> 5, lane = tid & 31;
    const int wm   = wid / WGN, wn = wid % WGN;
    const int bm   = blockIdx.y * BM;
    const int bn   = blockIdx.x * BN;
    const int z    = blockIdx.z;

    const size_t offA = (size_t)(z & 15) * zsA1 + (size_t)(z >> 4) * zsA2;
    const size_t offB = (size_t)(z & 15) * zsB1 + (size_t)(z >> 4) * zsB2;
    const size_t offC = (size_t)(z & 15) * zsC1 + (size_t)(z >> 4) * zsC2;
    const __nv_bfloat16* pAh = Ahi + offA;
    const __nv_bfloat16* pAl = Alo + offA;
    const __nv_bfloat16* pBh = Bhi + offB;
    const __nv_bfloat16* pBl = Blo + offB;

    float acc[MT][NT][4];
#pragma unroll
    for (int i = 0; i < MT; i++)
#pragma unroll
        for (int j = 0; j < NT; j++)
#pragma unroll
            for (int q = 0; q < 4; q++) acc[i][j][q] = 0.0f;

    const int NC = K / BK;

    auto issue = [&](int c) {
        const uint32_t sb = sbase + (uint32_t)(c & 1) * STAGE;
        const int k0 = c * BK;
#pragma unroll
        for (int it = 0; it < CHUNKS / 256; it++) {
            int idx = tid + it * 256;
            int r4 = idx >> 2, kc = idx & 3;
            const __nv_bfloat16* src;
            uint32_t dst;
            if (r4 < BM) {
                src = pAh + (size_t)(bm + r4) * lda + k0 + kc * 8;
                dst = sb + (uint32_t)(r4 * (LDSR * 2) + kc * 16);
            } else if (r4 < 2 * BM) {
                int r = r4 - BM;
                src = pAl + (size_t)(bm + r) * lda + k0 + kc * 8;
                dst = sb + A_BYTES + (uint32_t)(r * (LDSR * 2) + kc * 16);
            } else if (r4 < 2 * BM + BN) {
                int r = r4 - 2 * BM;
                src = pBh + (size_t)(bn + r) * ldb + k0 + kc * 8;
                dst = sb + 2 * A_BYTES + (uint32_t)(r * (LDSR * 2) + kc * 16);
            } else {
                int r = r4 - 2 * BM - BN;
                src = pBl + (size_t)(bn + r) * ldb + k0 + kc * 8;
                dst = sb + 2 * A_BYTES + B_BYTES + (uint32_t)(r * (LDSR * 2) + kc * 16);
            }
            cp16(dst, src);
        }
        CP_COMMIT();
    };

    issue(0);

    for (int c = 0; c < NC; c++) {
        if (c + 1 < NC) { issue(c + 1); CP_WAIT(1); }
        else            { CP_WAIT(0); }
        __syncthreads();

        const uint32_t sA  = sbase + (uint32_t)(c & 1) * STAGE;
        const uint32_t sB  = sA + 2 * A_BYTES;

        const int arow = lane & 15;
        const int acb  = (lane >> 4) * 8;
        const int brow = lane & 7;
        const int bcb  = ((lane >> 3) & 1) * 8;

#pragma unroll
        for (int ks = 0; ks < 2; ks++) {
            uint32_t ahi[MT][4], alo[MT][4], bhi[NT][2], blo[NT][2];
#pragma unroll
            for (int mt = 0; mt < MT; mt++) {
                uint32_t off = (uint32_t)(((wm * WTM + mt * 16 + arow) * LDSR
                                           + ks * 16 + acb) * 2);
                LDSM_X4(ahi[mt], sA + off);
                LDSM_X4(alo[mt], sA + A_BYTES + off);
            }
#pragma unroll
            for (int nt = 0; nt < NT; nt++) {
                uint32_t off = (uint32_t)(((wn * WTN + nt * 8 + brow) * LDSR
                                           + ks * 16 + bcb) * 2);
                LDSM_X2(bhi[nt], sB + off);
                LDSM_X2(blo[nt], sB + B_BYTES + off);
            }
#pragma unroll
            for (int mt = 0; mt < MT; mt++)
#pragma unroll
                for (int nt = 0; nt < NT; nt++) {
                    MMA16816(acc[mt][nt], ahi[mt], bhi[nt]);
                    MMA16816(acc[mt][nt], ahi[mt], blo[nt]);
                    MMA16816(acc[mt][nt], alo[mt], bhi[nt]);
                }
        }
        __syncthreads();
    }

    const int erow = lane >> 2;
    const int ecol = 2 * (lane & 3);
#pragma unroll
    for (int mt = 0; mt < MT; mt++) {
        const int row = bm + wm * WTM + mt * 16 + erow;
#pragma unroll
        for (int nt = 0; nt < NT; nt++) {
            const int col = bn + wn * WTN + nt * 8 + ecol;
            if constexpr (OUT16) {
                __nv_bfloat162 l0, l1;
                __nv_bfloat162 h0 = split_pair(acc[mt][nt][0] * scale,
                                               acc[mt][nt][1] * scale, l0);
                __nv_bfloat162 h1 = split_pair(acc[mt][nt][2] * scale,
                                               acc[mt][nt][3] * scale, l1);
                size_t o0 = offC + (size_t)row * ldc + col;
                size_t o1 = offC + (size_t)(row + 8) * ldc + col;
                *(__nv_bfloat162*)(Chi + o0) = h0;
                *(__nv_bfloat162*)(Clo + o0) = l0;
                *(__nv_bfloat162*)(Chi + o1) = h1;
                *(__nv_bfloat162*)(Clo + o1) = l1;
            } else {
                float* pC = C + offC;
                *(float2*)(pC + (size_t)row * ldc + col) =
                    make_float2(acc[mt][nt][0] * scale, acc[mt][nt][1] * scale);
                *(float2*)(pC + (size_t)(row + 8) * ldc + col) =
                    make_float2(acc[mt][nt][2] * scale, acc[mt][nt][3] * scale);
            }
        }
    }
}

// ---------------------------------------------------------------------------
// Fused head-softmax + attn@V.
// grid (S/32, B), 256 threads. Per iter (KT=32 keys):
//   cp.async-staged scores tile [16h][32q][32k] fp32 (double buffered)
//   -> softmax across h -> p hi/lo bf16 smem -> per-head p@Vt HMMA x3.
// Output x written directly as bf16 hi/lo [4096, 1024].
// ---------------------------------------------------------------------------
constexpr int QT = 32, KT = 32;
constexpr int PPAD = 40;
constexpr int SC_STAGE_BYTES = H_ * QT * KT * 4;               // 65536
constexpr int P_BYTES = H_ * QT * PPAD * 2;                    // 40960
constexpr int FUSED_SMEM = 2 * SC_STAGE_BYTES + 2 * P_BYTES;   // 212992

__global__ __launch_bounds__(256, 1) void fused_softmax_av(
    const float* __restrict__ att,
    const __nv_bfloat16* __restrict__ vth, const __nv_bfloat16* __restrict__ vtl,
    __nv_bfloat16* __restrict__ xh, __nv_bfloat16* __restrict__ xl)
{
    extern __shared__ char smem_raw[];
    const uint32_t sc_base = smem_u32(smem_raw);
    const uint32_t ph_base = sc_base + 2 * SC_STAGE_BYTES;
    const uint32_t pl_base = ph_base + P_BYTES;
    __nv_bfloat16* ph = (__nv_bfloat16*)(smem_raw + 2 * SC_STAGE_BYTES);
    __nv_bfloat16* pl = ph + H_ * QT * PPAD;
    float* scf = (float*)smem_raw;

    const int tid  = threadIdx.x;
    const int wid  = tid >> 5, lane = tid & 31;
    const int q0   = blockIdx.x * QT;
    const int b    = blockIdx.y;

    const float* attb = att + (size_t)b * H_ * SS_;
    const __nv_bfloat16* vhb = vth + (size_t)b * H_ * 64 * S_;
    const __nv_bfloat16* vlb = vtl + (size_t)b * H_ * 64 * S_;

    const int h0 = wid * 2;   // two heads per warp

    float acc[2][2][8][4];
#pragma unroll
    for (int a = 0; a < 2; a++)
#pragma unroll
        for (int m = 0; m < 2; m++)
#pragma unroll
            for (int n = 0; n < 8; n++)
#pragma unroll
                for (int q = 0; q < 4; q++) acc[a][m][n][q] = 0.0f;

    const int NC = S_ / KT;   // 64

    auto issue = [&](int c) {
        const uint32_t sb = sc_base + (uint32_t)(c & 1) * SC_STAGE_BYTES;
        const int k0 = c * KT;
#pragma unroll
        for (int t = 0; t < 16; t++) {
            int idx = tid + t * 256;        // 0..4095 (16B chunks)
            int row = idx >> 3;             // h*32 + q
            int kc  = (idx & 7) * 4;        // float offset
            int h = row >> 5, q = row & 31;
            const float* src = attb + (size_t)h * SS_ + (size_t)(q0 + q) * S_ + k0 + kc;
            cp16(sb + (uint32_t)(idx * 16), src);
        }
        CP_COMMIT();
    };

    issue(0);

    for (int c = 0; c < NC; c++) {
        if (c + 1 < NC) { issue(c + 1); CP_WAIT(1); }
        else            { CP_WAIT(0); }
        __syncthreads();

        // ---- softmax across heads (pointwise in q,k) ----
        const float* scs = scf + (size_t)(c & 1) * (SC_STAGE_BYTES / 4);
#pragma unroll
        for (int t = 0; t < 4; t++) {
            int pidx = tid + t * 256;       // 0..1023
            int q = pidx >> 5, k = pidx & 31;
            float v[H_];
            float m = -1e30f;
#pragma unroll
            for (int h = 0; h < H_; h++) {
                v[h] = scs[(h * QT + q) * KT + k];
                m = fmaxf(m, v[h]);
            }
            float s = 0.0f;
#pragma unroll
            for (int h = 0; h < H_; h++) { v[h] = __expf(v[h] - m); s += v[h]; }
            float inv = 1.0f / s;
#pragma unroll
            for (int h = 0; h < H_; h++) {
                float p = v[h] * inv;
                __nv_bfloat16 hi = __float2bfloat16(p);
                int o = (h * QT + q) * PPAD + k;
                ph[o] = hi;
                pl[o] = __float2bfloat16(p - __bfloat162float(hi));
            }
        }
        __syncthreads();

        // ---- per-head p @ Vt^T (x3) ----
        const int k0 = c * KT;
        const int arow = lane & 15;
        const int acb  = (lane >> 4) * 8;
        const int bn   = lane >> 2;       // n within 8
        const int bk   = (lane & 3) * 2;  // k pair
#pragma unroll
        for (int hh = 0; hh < 2; hh++) {
            const int h = h0 + hh;
            const __nv_bfloat16* vh = vhb + (size_t)h * 64 * S_ + k0;
            const __nv_bfloat16* vl = vlb + (size_t)h * 64 * S_ + k0;
#pragma unroll
            for (int ks = 0; ks < 2; ks++) {
                uint32_t a_hi[2][4], a_lo[2][4];
#pragma unroll
                for (int mt = 0; mt < 2; mt++) {
                    uint32_t off = (uint32_t)(((h * QT + mt * 16 + arow) * PPAD
                                               + ks * 16 + acb) * 2);
                    LDSM_X4(a_hi[mt], ph_base + off);
                    LDSM_X4(a_lo[mt], pl_base + off);
                }
#pragma unroll
                for (int nt = 0; nt < 8; nt++) {
                    const int n = nt * 8 + bn;
                    const __nv_bfloat16* sh = vh + (size_t)n * S_ + ks * 16 + bk;
                    const __nv_bfloat16* sl = vl + (size_t)n * S_ + ks * 16 + bk;
                    uint32_t b_hi[2], b_lo[2];
                    b_hi[0] = *(const uint32_t*)sh;
                    b_hi[1] = *(const uint32_t*)(sh + 8);
                    b_lo[0] = *(const uint32_t*)sl;
                    b_lo[1] = *(const uint32_t*)(sl + 8);
#pragma unroll
                    for (int mt = 0; mt < 2; mt++) {
                        MMA16816(acc[hh][mt][nt], a_hi[mt], b_hi);
                        MMA16816(acc[hh][mt][nt], a_hi[mt], b_lo);
                        MMA16816(acc[hh][mt][nt], a_lo[mt], b_hi);
                    }
                }
            }
        }
        __syncthreads();
    }

    // ---- epilogue: x -> bf16 hi/lo ----
    const int erow = lane >> 2;
    const int ecol = 2 * (lane & 3);
#pragma unroll
    for (int hh = 0; hh < 2; hh++) {
#pragma unroll
        for (int mt = 0; mt < 2; mt++) {
            const int row = q0 + mt * 16 + erow;
#pragma unroll
            for (int nt = 0; nt < 8; nt++) {
                const int col = (h0 + hh) * 64 + nt * 8 + ecol;
                __nv_bfloat162 l0, l1;
                __nv_bfloat162 hv0 = split_pair(acc[hh][mt][nt][0],
                                                acc[hh][mt][nt][1], l0);
                __nv_bfloat162 hv1 = split_pair(acc[hh][mt][nt][2],
                                                acc[hh][mt][nt][3], l1);
                size_t o0 = ((size_t)b * S_ + row) * D_ + col;
                size_t o1 = ((size_t)b * S_ + row + 8) * D_ + col;
                *(__nv_bfloat162*)(xh + o0) = hv0;
                *(__nv_bfloat162*)(xl + o0) = l0;
                *(__nv_bfloat162*)(xh + o1) = hv1;
                *(__nv_bfloat162*)(xl + o1) = l1;
            }
        }
    }
}

// ---------------------------------------------------------------------------
extern "C" void kernel_launch(void* const* d_in, const int* in_sizes, int n_in,
                              void* d_out, int out_size)
{
    (void)in_sizes; (void)n_in; (void)out_size;
    const float* qi = (const float*)d_in[0];
    const float* ki = (const float*)d_in[1];
    const float* vi = (const float*)d_in[2];
    // d_in[3] = mask: reference discards masked_fill -> unused
    const float* Wq = (const float*)d_in[4];
    const float* Wk = (const float*)d_in[5];
    const float* Wv = (const float*)d_in[6];
    const float* Wo = (const float*)d_in[7];
    float* out = (float*)d_out;

    float *gv, *gatt;
    cudaGetSymbolAddress((void**)&gv,   g_v);
    cudaGetSymbolAddress((void**)&gatt, g_att);

    __nv_bfloat16 *qih, *qil, *kih, *kil, *vih, *vil;
    __nv_bfloat16 *qh, *ql, *kh, *kl, *xh, *xl, *vth, *vtl;
    __nv_bfloat16 *wqh, *wql, *wkh, *wkl, *wvh, *wvl, *woh, *wol;
    cudaGetSymbolAddress((void**)&qih, g_qi_hi); cudaGetSymbolAddress((void**)&qil, g_qi_lo);
    cudaGetSymbolAddress((void**)&kih, g_ki_hi); cudaGetSymbolAddress((void**)&kil, g_ki_lo);
    cudaGetSymbolAddress((void**)&vih, g_vi_hi); cudaGetSymbolAddress((void**)&vil, g_vi_lo);
    cudaGetSymbolAddress((void**)&qh,  g_q_hi);  cudaGetSymbolAddress((void**)&ql,  g_q_lo);
    cudaGetSymbolAddress((void**)&kh,  g_k_hi);  cudaGetSymbolAddress((void**)&kl,  g_k_lo);
    cudaGetSymbolAddress((void**)&xh,  g_x_hi);  cudaGetSymbolAddress((void**)&xl,  g_x_lo);
    cudaGetSymbolAddress((void**)&vth, g_vt_hi); cudaGetSymbolAddress((void**)&vtl, g_vt_lo);
    cudaGetSymbolAddress((void**)&wqh, g_wq_hi); cudaGetSymbolAddress((void**)&wql, g_wq_lo);
    cudaGetSymbolAddress((void**)&wkh, g_wk_hi); cudaGetSymbolAddress((void**)&wkl, g_wk_lo);
    cudaGetSymbolAddress((void**)&wvh, g_wv_hi); cudaGetSymbolAddress((void**)&wvl, g_wv_lo);
    cudaGetSymbolAddress((void**)&woh, g_wo_hi); cudaGetSymbolAddress((void**)&wol, g_wo_lo);

    auto* gemm_f32 = gemm_bf16x3_mma<128, 2, 4, 0>;
    auto* gemm_b16 = gemm_bf16x3_mma<128, 2, 4, 1>;
    constexpr int SMEM_BIG = 2 * (2 * 128 * 40 * 2 + 2 * 128 * 40 * 2); // 81920
    cudaFuncSetAttribute(gemm_f32, cudaFuncAttributeMaxDynamicSharedMemorySize, SMEM_BIG);
    cudaFuncSetAttribute(gemm_b16, cudaFuncAttributeMaxDynamicSharedMemorySize, SMEM_BIG);
    cudaFuncSetAttribute(fused_softmax_av,
                         cudaFuncAttributeMaxDynamicSharedMemorySize, FUSED_SMEM);

    const int nInp4 = (M_ * D_) / 4;
    const int nW4   = (D_ * D_) / 4;

    // 1) split inputs + weights to bf16 hi/lo
    split_bf16_kernel<<<nInp4 / 256, 256>>>((const float4*)qi, (__nv_bfloat162*)qih, (__nv_bfloat162*)qil, nInp4);
    split_bf16_kernel<<<nInp4 / 256, 256>>>((const float4*)ki, (__nv_bfloat162*)kih, (__nv_bfloat162*)kil, nInp4);
    split_bf16_kernel<<<nInp4 / 256, 256>>>((const float4*)vi, (__nv_bfloat162*)vih, (__nv_bfloat162*)vil, nInp4);
    split_bf16_kernel<<<nW4 / 256, 256>>>((const float4*)Wq, (__nv_bfloat162*)wqh, (__nv_bfloat162*)wql, nW4);
    split_bf16_kernel<<<nW4 / 256, 256>>>((const float4*)Wk, (__nv_bfloat162*)wkh, (__nv_bfloat162*)wkl, nW4);
    split_bf16_kernel<<<nW4 / 256, 256>>>((const float4*)Wv, (__nv_bfloat162*)wvh, (__nv_bfloat162*)wvl, nW4);
    split_bf16_kernel<<<nW4 / 256, 256>>>((const float4*)Wo, (__nv_bfloat162*)woh, (__nv_bfloat162*)wol, nW4);

    // 2) projections: Q,K emit bf16 hi/lo directly; V emits fp32 for transpose
    dim3 gproj(D_ / 128, M_ / 128, 1);
    gemm_b16<<<gproj, 256, SMEM_BIG>>>(qih, qil, wqh, wql, nullptr, qh, ql,
                                       D_, D_, D_, D_, 0, 0, 0, 0, 0, 0, 1.0f);
    gemm_b16<<<gproj, 256, SMEM_BIG>>>(kih, kil, wkh, wkl, nullptr, kh, kl,
                                       D_, D_, D_, D_, 0, 0, 0, 0, 0, 0, 1.0f);
    gemm_f32<<<gproj, 256, SMEM_BIG>>>(vih, vil, wvh, wvl, gv, nullptr, nullptr,
                                       D_, D_, D_, D_, 0, 0, 0, 0, 0, 0, 1.0f);

    // 3) transpose+split v -> [bh][64][2048]
    dim3 gtr(D_ / 32, S_ / 32, B_);
    transpose_split_v<<<gtr, 256>>>(gv, vth, vtl);

    // 4) scores[bh] = (Q_h @ K_h^T) / 8
    dim3 gsc(S_ / 128, S_ / 128, B_ * H_);
    gemm_f32<<<gsc, 256, SMEM_BIG>>>(qh, ql, kh, kl, gatt, nullptr, nullptr,
                                     64, D_, D_, S_,
                                     64, (size_t)S_ * D_,
                                     64, (size_t)S_ * D_,
                                     SS_, (size_t)H_ * SS_, 0.125f);

    // 5) fused softmax-over-h + attn@V -> x (bf16 hi/lo)
    dim3 gfa(S_ / QT, B_);
    fused_softmax_av<<<gfa, 256, FUSED_SMEM>>>(gatt, vth, vtl, xh, xl);

    // 6) out = x @ Wo^T
    gemm_f32<<<gproj, 256, SMEM_BIG>>>(xh, xl, woh, wol, out, nullptr, nullptr,
                                       D_, D_, D_, D_, 0, 0, 0, 0, 0, 0, 1.0f);
}

// round 5
// speedup vs baseline: 1.1803x; 1.1803x over previous
#include <cuda_runtime.h>
#include <cuda_bf16.h>
#include <cstdint>

// Problem constants (fixed shapes)
constexpr int B_  = 2;
constexpr int S_  = 2048;
constexpr int D_  = 1024;
constexpr int H_  = 16;
constexpr int M_  = B_ * S_;            // 4096
constexpr size_t SS_ = (size_t)S_ * S_; // 4M

// ---------------------------------------------------------------------------
// Device-global scratch
// ---------------------------------------------------------------------------
__device__ float g_v[(size_t)M_ * D_];
__device__ float g_att[(size_t)B_ * H_ * SS_];            // 512 MB fp32 scores

__device__ __nv_bfloat16 g_att_hi[(size_t)B_ * H_ * SS_]; // 256 MB
__device__ __nv_bfloat16 g_att_lo[(size_t)B_ * H_ * SS_];

__device__ __nv_bfloat16 g_qi_hi[(size_t)M_ * D_], g_qi_lo[(size_t)M_ * D_];
__device__ __nv_bfloat16 g_ki_hi[(size_t)M_ * D_], g_ki_lo[(size_t)M_ * D_];
__device__ __nv_bfloat16 g_vi_hi[(size_t)M_ * D_], g_vi_lo[(size_t)M_ * D_];
__device__ __nv_bfloat16 g_q_hi [(size_t)M_ * D_], g_q_lo [(size_t)M_ * D_];
__device__ __nv_bfloat16 g_k_hi [(size_t)M_ * D_], g_k_lo [(size_t)M_ * D_];
__device__ __nv_bfloat16 g_x_hi [(size_t)M_ * D_], g_x_lo [(size_t)M_ * D_];
__device__ __nv_bfloat16 g_vt_hi[(size_t)B_ * H_ * 64 * S_];  // [bh][64][2048]
__device__ __nv_bfloat16 g_vt_lo[(size_t)B_ * H_ * 64 * S_];
__device__ __nv_bfloat16 g_wq_hi[(size_t)D_ * D_], g_wq_lo[(size_t)D_ * D_];
__device__ __nv_bfloat16 g_wk_hi[(size_t)D_ * D_], g_wk_lo[(size_t)D_ * D_];
__device__ __nv_bfloat16 g_wv_hi[(size_t)D_ * D_], g_wv_lo[(size_t)D_ * D_];
__device__ __nv_bfloat16 g_wo_hi[(size_t)D_ * D_], g_wo_lo[(size_t)D_ * D_];

// ---------------------------------------------------------------------------
// PTX helpers (compute_103-baseline safe: mma.sync / ldmatrix / cp.async)
// ---------------------------------------------------------------------------
__device__ __forceinline__ uint32_t smem_u32(const void* p) {
    uint32_t a;
    asm("{ .reg .u64 t; cvta.to.shared.u64 t, %1; cvt.u32.u64 %0, t; }"
        : "=r"(a) : "l"(p));
    return a;
}
__device__ __forceinline__ void cp16(uint32_t dst, const void* src) {
    asm volatile("cp.async.cg.shared.global [%0], [%1], 16;"
                 :: "r"(dst), "l"(src));
}
#define CP_COMMIT() asm volatile("cp.async.commit_group;" ::: "memory")
#define CP_WAIT(n)  asm volatile("cp.async.wait_group %0;" :: "n"(n) : "memory")

#define LDSM_X4(r, addr)                                                       \
    asm volatile("ldmatrix.sync.aligned.m8n8.x4.shared.b16 {%0,%1,%2,%3},[%4];"\
                 : "=r"((r)[0]), "=r"((r)[1]), "=r"((r)[2]), "=r"((r)[3])      \
                 : "r"(addr))
#define LDSM_X2(r, addr)                                                       \
    asm volatile("ldmatrix.sync.aligned.m8n8.x2.shared.b16 {%0,%1},[%2];"      \
                 : "=r"((r)[0]), "=r"((r)[1]) : "r"(addr))
#define MMA16816(c, a, b)                                                      \
    asm volatile("mma.sync.aligned.m16n8k16.row.col.f32.bf16.bf16.f32 "        \
                 "{%0,%1,%2,%3},{%4,%5,%6,%7},{%8,%9},{%0,%1,%2,%3};"          \
                 : "+f"((c)[0]), "+f"((c)[1]), "+f"((c)[2]), "+f"((c)[3])      \
                 : "r"((a)[0]), "r"((a)[1]), "r"((a)[2]), "r"((a)[3]),         \
                   "r"((b)[0]), "r"((b)[1]))

__device__ __forceinline__ __nv_bfloat162 split_pair(float a, float b,
                                                     __nv_bfloat162& lo) {
    __nv_bfloat16 ha = __float2bfloat16(a);
    __nv_bfloat16 hb = __float2bfloat16(b);
    lo = __nv_bfloat162(__float2bfloat16(a - __bfloat162float(ha)),
                        __float2bfloat16(b - __bfloat162float(hb)));
    return __nv_bfloat162(ha, hb);
}

__device__ __forceinline__ void split_store4(const float4* x,
                                             __nv_bfloat162* hi,
                                             __nv_bfloat162* lo, int i) {
    float4 v = x[i];
    __nv_bfloat162 l0, l1;
    __nv_bfloat162 h0 = split_pair(v.x, v.y, l0);
    __nv_bfloat162 h1 = split_pair(v.z, v.w, l1);
    hi[2 * i] = h0; hi[2 * i + 1] = h1;
    lo[2 * i] = l0; lo[2 * i + 1] = l1;
}

// ---------------------------------------------------------------------------
// Fused splits: 3 input tensors (grid.y selects), 4 weight tensors
// ---------------------------------------------------------------------------
__global__ __launch_bounds__(256) void split3_kernel(
    const float4* __restrict__ s0, const float4* __restrict__ s1,
    const float4* __restrict__ s2,
    __nv_bfloat162* __restrict__ h0, __nv_bfloat162* __restrict__ l0,
    __nv_bfloat162* __restrict__ h1, __nv_bfloat162* __restrict__ l1,
    __nv_bfloat162* __restrict__ h2, __nv_bfloat162* __restrict__ l2)
{
    int i = blockIdx.x * 256 + threadIdx.x;   // < M_*D_/4
    const float4* s = blockIdx.y == 0 ? s0 : blockIdx.y == 1 ? s1 : s2;
    __nv_bfloat162* h = blockIdx.y == 0 ? h0 : blockIdx.y == 1 ? h1 : h2;
    __nv_bfloat162* l = blockIdx.y == 0 ? l0 : blockIdx.y == 1 ? l1 : l2;
    split_store4(s, h, l, i);
}

__global__ __launch_bounds__(256) void split4_kernel(
    const float4* __restrict__ s0, const float4* __restrict__ s1,
    const float4* __restrict__ s2, const float4* __restrict__ s3,
    __nv_bfloat162* __restrict__ h0, __nv_bfloat162* __restrict__ l0,
    __nv_bfloat162* __restrict__ h1, __nv_bfloat162* __restrict__ l1,
    __nv_bfloat162* __restrict__ h2, __nv_bfloat162* __restrict__ l2,
    __nv_bfloat162* __restrict__ h3, __nv_bfloat162* __restrict__ l3)
{
    int i = blockIdx.x * 256 + threadIdx.x;   // < D_*D_/4
    const float4* s; __nv_bfloat162 *h, *l;
    switch (blockIdx.y) {
        case 0:  s = s0; h = h0; l = l0; break;
        case 1:  s = s1; h = h1; l = l1; break;
        case 2:  s = s2; h = h2; l = l2; break;
        default: s = s3; h = h3; l = l3; break;
    }
    split_store4(s, h, l, i);
}

// ---------------------------------------------------------------------------
// V [b, k(2048), d(1024)] fp32  ->  Vt hi/lo [bh, d(64), k(2048)] bf16
// ---------------------------------------------------------------------------
__global__ __launch_bounds__(256) void transpose_split_v(
    const float* __restrict__ V, __nv_bfloat16* __restrict__ hi,
    __nv_bfloat16* __restrict__ lo)
{
    __shared__ float t[32][33];
    const int b  = blockIdx.z;
    const int k0 = blockIdx.y * 32;
    const int d0 = blockIdx.x * 32;
    const int tx = threadIdx.x & 31, ty = threadIdx.x >> 5;  // 32 x 8
#pragma unroll
    for (int i = 0; i < 4; i++) {
        int k = k0 + ty + i * 8;
        t[ty + i * 8][tx] = V[((size_t)b * S_ + k) * D_ + d0 + tx];
    }
    __syncthreads();
#pragma unroll
    for (int i = 0; i < 4; i++) {
        int d = d0 + ty + i * 8;
        int h = d >> 6, dh = d & 63;
        float val = t[tx][ty + i * 8];
        size_t o = ((size_t)(b * H_ + h) * 64 + dh) * S_ + k0 + tx;
        __nv_bfloat16 hv = __float2bfloat16(val);
        hi[o] = hv;
        lo[o] = __float2bfloat16(val - __bfloat162float(hv));
    }
}

// ---------------------------------------------------------------------------
// Generic NT bf16x3 GEMM: C[M,N](+scale) = (Ahi+Alo)[M,K] @ (Bhi+Blo)[N,K]^T
// OUT16=0: fp32 C.  OUT16=1: bf16 hi/lo (Chi, Clo).
// ---------------------------------------------------------------------------
template<int BN, int WGM, int WGN, int OUT16>
__global__ __launch_bounds__(256, 1) void gemm_bf16x3_mma(
    const __nv_bfloat16* __restrict__ Ahi, const __nv_bfloat16* __restrict__ Alo,
    const __nv_bfloat16* __restrict__ Bhi, const __nv_bfloat16* __restrict__ Blo,
    float* __restrict__ C, __nv_bfloat16* __restrict__ Chi,
    __nv_bfloat16* __restrict__ Clo, int K, int lda, int ldb, int ldc,
    size_t zsA1, size_t zsA2, size_t zsB1, size_t zsB2,
    size_t zsC1, size_t zsC2, float scale)
{
    constexpr int BM  = 128, BK = 32;
    constexpr int WTM = BM / WGM;
    constexpr int WTN = BN / WGN;
    constexpr int MT  = WTM / 16;
    constexpr int NT  = WTN / 8;
    constexpr int LDSR = BK + 8;
    constexpr int A_BYTES = BM * LDSR * 2;
    constexpr int B_BYTES = BN * LDSR * 2;
    constexpr int STAGE   = 2 * A_BYTES + 2 * B_BYTES;
    constexpr int CHUNKS  = (2 * BM + 2 * BN) * 4;

    extern __shared__ char smem_raw[];
    const uint32_t sbase = smem_u32(smem_raw);

    const int tid  = threadIdx.x;
    const int wid  = tid >> 5, lane = tid & 31;
    const int wm   = wid / WGN, wn = wid % WGN;
    const int bm   = blockIdx.y * BM;
    const int bn   = blockIdx.x * BN;
    const int z    = blockIdx.z;

    const size_t offA = (size_t)(z & 15) * zsA1 + (size_t)(z >> 4) * zsA2;
    const size_t offB = (size_t)(z & 15) * zsB1 + (size_t)(z >> 4) * zsB2;
    const size_t offC = (size_t)(z & 15) * zsC1 + (size_t)(z >> 4) * zsC2;
    const __nv_bfloat16* pAh = Ahi + offA;
    const __nv_bfloat16* pAl = Alo + offA;
    const __nv_bfloat16* pBh = Bhi + offB;
    const __nv_bfloat16* pBl = Blo + offB;

    float acc[MT][NT][4];
#pragma unroll
    for (int i = 0; i < MT; i++)
#pragma unroll
        for (int j = 0; j < NT; j++)
#pragma unroll
            for (int q = 0; q < 4; q++) acc[i][j][q] = 0.0f;

    const int NC = K / BK;

    auto issue = [&](int c) {
        const uint32_t sb = sbase + (uint32_t)(c & 1) * STAGE;
        const int k0 = c * BK;
#pragma unroll
        for (int it = 0; it < CHUNKS / 256; it++) {
            int idx = tid + it * 256;
            int r4 = idx >> 2, kc = idx & 3;
            const __nv_bfloat16* src;
            uint32_t dst;
            if (r4 < BM) {
                src = pAh + (size_t)(bm + r4) * lda + k0 + kc * 8;
                dst = sb + (uint32_t)(r4 * (LDSR * 2) + kc * 16);
            } else if (r4 < 2 * BM) {
                int r = r4 - BM;
                src = pAl + (size_t)(bm + r) * lda + k0 + kc * 8;
                dst = sb + A_BYTES + (uint32_t)(r * (LDSR * 2) + kc * 16);
            } else if (r4 < 2 * BM + BN) {
                int r = r4 - 2 * BM;
                src = pBh + (size_t)(bn + r) * ldb + k0 + kc * 8;
                dst = sb + 2 * A_BYTES + (uint32_t)(r * (LDSR * 2) + kc * 16);
            } else {
                int r = r4 - 2 * BM - BN;
                src = pBl + (size_t)(bn + r) * ldb + k0 + kc * 8;
                dst = sb + 2 * A_BYTES + B_BYTES + (uint32_t)(r * (LDSR * 2) + kc * 16);
            }
            cp16(dst, src);
        }
        CP_COMMIT();
    };

    issue(0);

    for (int c = 0; c < NC; c++) {
        if (c + 1 < NC) { issue(c + 1); CP_WAIT(1); }
        else            { CP_WAIT(0); }
        __syncthreads();

        const uint32_t sA  = sbase + (uint32_t)(c & 1) * STAGE;
        const uint32_t sB  = sA + 2 * A_BYTES;

        const int arow = lane & 15;
        const int acb  = (lane >> 4) * 8;
        const int brow = lane & 7;
        const int bcb  = ((lane >> 3) & 1) * 8;

#pragma unroll
        for (int ks = 0; ks < 2; ks++) {
            uint32_t ahi[MT][4], alo[MT][4], bhi[NT][2], blo[NT][2];
#pragma unroll
            for (int mt = 0; mt < MT; mt++) {
                uint32_t off = (uint32_t)(((wm * WTM + mt * 16 + arow) * LDSR
                                           + ks * 16 + acb) * 2);
                LDSM_X4(ahi[mt], sA + off);
                LDSM_X4(alo[mt], sA + A_BYTES + off);
            }
#pragma unroll
            for (int nt = 0; nt < NT; nt++) {
                uint32_t off = (uint32_t)(((wn * WTN + nt * 8 + brow) * LDSR
                                           + ks * 16 + bcb) * 2);
                LDSM_X2(bhi[nt], sB + off);
                LDSM_X2(blo[nt], sB + B_BYTES + off);
            }
#pragma unroll
            for (int mt = 0; mt < MT; mt++)
#pragma unroll
                for (int nt = 0; nt < NT; nt++) {
                    MMA16816(acc[mt][nt], ahi[mt], bhi[nt]);
                    MMA16816(acc[mt][nt], ahi[mt], blo[nt]);
                    MMA16816(acc[mt][nt], alo[mt], bhi[nt]);
                }
        }
        __syncthreads();
    }

    const int erow = lane >> 2;
    const int ecol = 2 * (lane & 3);
#pragma unroll
    for (int mt = 0; mt < MT; mt++) {
        const int row = bm + wm * WTM + mt * 16 + erow;
#pragma unroll
        for (int nt = 0; nt < NT; nt++) {
            const int col = bn + wn * WTN + nt * 8 + ecol;
            if constexpr (OUT16) {
                __nv_bfloat162 l0, l1;
                __nv_bfloat162 h0 = split_pair(acc[mt][nt][0] * scale,
                                               acc[mt][nt][1] * scale, l0);
                __nv_bfloat162 h1 = split_pair(acc[mt][nt][2] * scale,
                                               acc[mt][nt][3] * scale, l1);
                size_t o0 = offC + (size_t)row * ldc + col;
                size_t o1 = offC + (size_t)(row + 8) * ldc + col;
                *(__nv_bfloat162*)(Chi + o0) = h0;
                *(__nv_bfloat162*)(Clo + o0) = l0;
                *(__nv_bfloat162*)(Chi + o1) = h1;
                *(__nv_bfloat162*)(Clo + o1) = l1;
            } else {
                float* pC = C + offC;
                *(float2*)(pC + (size_t)row * ldc + col) =
                    make_float2(acc[mt][nt][0] * scale, acc[mt][nt][1] * scale);
                *(float2*)(pC + (size_t)(row + 8) * ldc + col) =
                    make_float2(acc[mt][nt][2] * scale, acc[mt][nt][3] * scale);
            }
        }
    }
}

// ---------------------------------------------------------------------------
// softmax over the HEAD axis; emits attn as bf16 hi/lo
// ---------------------------------------------------------------------------
__global__ __launch_bounds__(256) void softmax_h_split(
    const float* __restrict__ att, __nv_bfloat16* __restrict__ hi,
    __nv_bfloat16* __restrict__ lo)
{
    size_t idx = (size_t)blockIdx.x * 256 + threadIdx.x;   // over B*S*S
    size_t b   = idx >> 22;
    size_t rem = idx & (SS_ - 1);
    size_t base = b * (size_t)H_ * SS_ + rem;

    float v[H_];
    float m = -1e30f;
#pragma unroll
    for (int h = 0; h < H_; h++) {
        v[h] = att[base + (size_t)h * SS_];
        m = fmaxf(m, v[h]);
    }
    float s = 0.0f;
#pragma unroll
    for (int h = 0; h < H_; h++) {
        v[h] = __expf(v[h] - m);
        s += v[h];
    }
    float inv = 1.0f / s;
#pragma unroll
    for (int h = 0; h < H_; h++) {
        float p = v[h] * inv;
        __nv_bfloat16 ph = __float2bfloat16(p);
        size_t o = base + (size_t)h * SS_;
        hi[o] = ph;
        lo[o] = __float2bfloat16(p - __bfloat162float(ph));
    }
}

// ---------------------------------------------------------------------------
extern "C" void kernel_launch(void* const* d_in, const int* in_sizes, int n_in,
                              void* d_out, int out_size)
{
    (void)in_sizes; (void)n_in; (void)out_size;
    const float* qi = (const float*)d_in[0];
    const float* ki = (const float*)d_in[1];
    const float* vi = (const float*)d_in[2];
    // d_in[3] = mask: reference discards masked_fill -> unused
    const float* Wq = (const float*)d_in[4];
    const float* Wk = (const float*)d_in[5];
    const float* Wv = (const float*)d_in[6];
    const float* Wo = (const float*)d_in[7];
    float* out = (float*)d_out;

    float *gv, *gatt;
    cudaGetSymbolAddress((void**)&gv,   g_v);
    cudaGetSymbolAddress((void**)&gatt, g_att);

    __nv_bfloat16 *qih, *qil, *kih, *kil, *vih, *vil;
    __nv_bfloat16 *qh, *ql, *kh, *kl, *xh, *xl, *vth, *vtl, *ath, *atl;
    __nv_bfloat16 *wqh, *wql, *wkh, *wkl, *wvh, *wvl, *woh, *wol;
    cudaGetSymbolAddress((void**)&qih, g_qi_hi); cudaGetSymbolAddress((void**)&qil, g_qi_lo);
    cudaGetSymbolAddress((void**)&kih, g_ki_hi); cudaGetSymbolAddress((void**)&kil, g_ki_lo);
    cudaGetSymbolAddress((void**)&vih, g_vi_hi); cudaGetSymbolAddress((void**)&vil, g_vi_lo);
    cudaGetSymbolAddress((void**)&qh,  g_q_hi);  cudaGetSymbolAddress((void**)&ql,  g_q_lo);
    cudaGetSymbolAddress((void**)&kh,  g_k_hi);  cudaGetSymbolAddress((void**)&kl,  g_k_lo);
    cudaGetSymbolAddress((void**)&xh,  g_x_hi);  cudaGetSymbolAddress((void**)&xl,  g_x_lo);
    cudaGetSymbolAddress((void**)&vth, g_vt_hi); cudaGetSymbolAddress((void**)&vtl, g_vt_lo);
    cudaGetSymbolAddress((void**)&ath, g_att_hi);cudaGetSymbolAddress((void**)&atl, g_att_lo);
    cudaGetSymbolAddress((void**)&wqh, g_wq_hi); cudaGetSymbolAddress((void**)&wql, g_wq_lo);
    cudaGetSymbolAddress((void**)&wkh, g_wk_hi); cudaGetSymbolAddress((void**)&wkl, g_wk_lo);
    cudaGetSymbolAddress((void**)&wvh, g_wv_hi); cudaGetSymbolAddress((void**)&wvl, g_wv_lo);
    cudaGetSymbolAddress((void**)&woh, g_wo_hi); cudaGetSymbolAddress((void**)&wol, g_wo_lo);

    auto* gemm_f32 = gemm_bf16x3_mma<128, 2, 4, 0>;
    auto* gemm_b16 = gemm_bf16x3_mma<128, 2, 4, 1>;
    auto* gemm_nar = gemm_bf16x3_mma<64, 4, 2, 1>;
    constexpr int SMEM_BIG = 2 * (2 * 128 * 40 * 2 + 2 * 128 * 40 * 2); // 81920
    constexpr int SMEM_NAR = 2 * (2 * 128 * 40 * 2 + 2 * 64 * 40 * 2);  // 61440
    cudaFuncSetAttribute(gemm_f32, cudaFuncAttributeMaxDynamicSharedMemorySize, SMEM_BIG);
    cudaFuncSetAttribute(gemm_b16, cudaFuncAttributeMaxDynamicSharedMemorySize, SMEM_BIG);
    cudaFuncSetAttribute(gemm_nar, cudaFuncAttributeMaxDynamicSharedMemorySize, SMEM_NAR);

    const int nInp4 = (M_ * D_) / 4;   // 1,048,576
    const int nW4   = (D_ * D_) / 4;   // 262,144

    // launch 0: split inputs (qi, ki, vi)
    dim3 gs3(nInp4 / 256, 3);
    split3_kernel<<<gs3, 256>>>((const float4*)qi, (const float4*)ki, (const float4*)vi,
        (__nv_bfloat162*)qih, (__nv_bfloat162*)qil,
        (__nv_bfloat162*)kih, (__nv_bfloat162*)kil,
        (__nv_bfloat162*)vih, (__nv_bfloat162*)vil);

    // launch 1: split weights (Wq, Wk, Wv, Wo)
    dim3 gs4(nW4 / 256, 4);
    split4_kernel<<<gs4, 256>>>((const float4*)Wq, (const float4*)Wk,
                                (const float4*)Wv, (const float4*)Wo,
        (__nv_bfloat162*)wqh, (__nv_bfloat162*)wql,
        (__nv_bfloat162*)wkh, (__nv_bfloat162*)wkl,
        (__nv_bfloat162*)wvh, (__nv_bfloat162*)wvl,
        (__nv_bfloat162*)woh, (__nv_bfloat162*)wol);

    // launches 2-4: projections (Q,K emit bf16 hi/lo directly; V fp32)
    dim3 gproj(D_ / 128, M_ / 128, 1);
    gemm_b16<<<gproj, 256, SMEM_BIG>>>(qih, qil, wqh, wql, nullptr, qh, ql,
                                       D_, D_, D_, D_, 0, 0, 0, 0, 0, 0, 1.0f);
    gemm_b16<<<gproj, 256, SMEM_BIG>>>(kih, kil, wkh, wkl, nullptr, kh, kl,
                                       D_, D_, D_, D_, 0, 0, 0, 0, 0, 0, 1.0f);
    gemm_f32<<<gproj, 256, SMEM_BIG>>>(vih, vil, wvh, wvl, gv, nullptr, nullptr,
                                       D_, D_, D_, D_, 0, 0, 0, 0, 0, 0, 1.0f);

    // launch 5 (ncu capture slot): scores[bh] = (Q_h @ K_h^T) / 8
    dim3 gsc(S_ / 128, S_ / 128, B_ * H_);
    gemm_f32<<<gsc, 256, SMEM_BIG>>>(qh, ql, kh, kl, gatt, nullptr, nullptr,
                                     64, D_, D_, S_,
                                     64, (size_t)S_ * D_,
                                     64, (size_t)S_ * D_,
                                     SS_, (size_t)H_ * SS_, 0.125f);

    // launch 6: transpose+split v -> [bh][64][2048]
    dim3 gtr(D_ / 32, S_ / 32, B_);
    transpose_split_v<<<gtr, 256>>>(gv, vth, vtl);

    // launch 7: softmax over heads -> attn hi/lo bf16
    int smx_blocks = (int)(((size_t)B_ * SS_) / 256);
    softmax_h_split<<<smx_blocks, 256>>>(gatt, ath, atl);

    // launch 8: x[bh] = attn[bh] @ Vt[bh]^T  (N=64), emits bf16 hi/lo
    dim3 gav(1, S_ / 128, B_ * H_);
    gemm_nar<<<gav, 256, SMEM_NAR>>>(ath, atl, vth, vtl, nullptr, xh, xl,
                                     S_, S_, S_, D_,
                                     SS_, (size_t)H_ * SS_,
                                     (size_t)64 * S_, (size_t)H_ * 64 * S_,
                                     64, (size_t)S_ * D_, 1.0f);

    // launch 9: out = x @ Wo^T
    gemm_f32<<<gproj, 256, SMEM_BIG>>>(xh, xl, woh, wol, out, nullptr, nullptr,
                                       D_, D_, D_, D_, 0, 0, 0, 0, 0, 0, 1.0f);
}